// round 2
// baseline (speedup 1.0000x reference)
#include <cuda_runtime.h>
#include <math.h>

#define B_   32
#define T_   1024
#define IN_  64
#define RES_ 2048
#define HID_ 512
#define OUT_ 64
#define BT_  (B_ * T_)
#define NCTA_ 128

// ---------------- scratch (device globals; no allocation allowed) ----------------
__device__ float g_UT[(size_t)T_ * RES_ * B_];   // UT[t][r][b]; overwritten in place with hsT
__device__ float g_h0[RES_ * B_];                // hT ping
__device__ float g_h1[RES_ * B_];                // hT pong
__device__ float g_a1[(size_t)BT_ * HID_];       // readout act 1, row-major [m][512], m = t*32+b
__device__ float g_a2[(size_t)BT_ * HID_];       // readout act 2
__device__ unsigned g_bar_count = 0;             // grid barrier arrive counter
__device__ unsigned g_bar_gen   = 0;             // grid barrier generation (monotonic)

// ---------------- U = x @ W_in^T, stored transposed: UT[t][r][b] ----------------
// grid: (16 r-tiles of 128, 1024 t), block 256
__global__ void __launch_bounds__(256) u_kernel(const float* __restrict__ x,
                                                const float* __restrict__ Win,
                                                float* __restrict__ UT)
{
    __shared__ float xS[IN_][B_];     // [i][b]
    __shared__ float wS[IN_][128];    // [i][r]
    const int t   = blockIdx.y;
    const int R0  = blockIdx.x * 128;
    const int tid = threadIdx.x;

    {
        int b  = tid >> 3;
        int iq = (tid & 7) * 8;
        const float* src = x + (size_t)b * (T_ * IN_) + (size_t)t * IN_ + iq;
        float4 v0 = *(const float4*)(src);
        float4 v1 = *(const float4*)(src + 4);
        xS[iq + 0][b] = v0.x; xS[iq + 1][b] = v0.y; xS[iq + 2][b] = v0.z; xS[iq + 3][b] = v0.w;
        xS[iq + 4][b] = v1.x; xS[iq + 5][b] = v1.y; xS[iq + 6][b] = v1.z; xS[iq + 7][b] = v1.w;
    }
    {
        int r  = tid >> 1;
        int ih = (tid & 1) * 32;
        const float* src = Win + (size_t)(R0 + r) * IN_ + ih;
#pragma unroll
        for (int j = 0; j < 32; j += 4) {
            float4 v = *(const float4*)(src + j);
            wS[ih + j + 0][r] = v.x; wS[ih + j + 1][r] = v.y;
            wS[ih + j + 2][r] = v.z; wS[ih + j + 3][r] = v.w;
        }
    }
    __syncthreads();

    const int tx = tid & 7, ty = tid >> 3;
    const int b0 = tx * 4, r0 = ty * 4;
    float acc[4][4];
#pragma unroll
    for (int i = 0; i < 4; i++)
#pragma unroll
        for (int j = 0; j < 4; j++) acc[i][j] = 0.f;

#pragma unroll
    for (int i = 0; i < IN_; i++) {
        float4 xv = *(const float4*)&xS[i][b0];
        float4 wv = *(const float4*)&wS[i][r0];
        float xa[4] = {xv.x, xv.y, xv.z, xv.w};
        float wa[4] = {wv.x, wv.y, wv.z, wv.w};
#pragma unroll
        for (int ri = 0; ri < 4; ri++)
#pragma unroll
            for (int bi = 0; bi < 4; bi++)
                acc[ri][bi] = fmaf(wa[ri], xa[bi], acc[ri][bi]);
    }
    float* dst = UT + (size_t)t * (RES_ * B_);
#pragma unroll
    for (int ri = 0; ri < 4; ri++) {
        float4 v = make_float4(acc[ri][0], acc[ri][1], acc[ri][2], acc[ri][3]);
        *(float4*)(dst + (size_t)(R0 + r0 + ri) * B_ + b0) = v;
    }
}

// ---------------- device-wide barrier (all NCTA_ CTAs resident: 1 CTA/SM) ----------------
__device__ __forceinline__ void grid_barrier()
{
    __threadfence();          // release: make this thread's writes visible chip-wide
    __syncthreads();          // all threads of CTA have fenced
    if (threadIdx.x == 0) {
        volatile unsigned* vgen = &g_bar_gen;
        unsigned old = *vgen;
        unsigned ticket = atomicAdd(&g_bar_count, 1u);
        if (ticket == NCTA_ - 1) {
            g_bar_count = 0;
            __threadfence();
            atomicAdd(&g_bar_gen, 1u);
        } else {
            while (*vgen == old) { __nanosleep(64); }
        }
        __threadfence();      // acquire
    }
    __syncthreads();
}

// ---------------- persistent ESN scan: all 1024 steps in ONE launch ----------------
// 128 CTAs x 512 threads. CTA owns 16 output rows n0..n0+15, W slice cached in SMEM.
// dynamic smem: wS[2048*16] (128KB) + red[16*16*32] (32KB) = 160KB -> 1 CTA/SM.
__global__ void __launch_bounds__(512) scan_persistent_kernel(const float* __restrict__ Wh,
                                                              float* __restrict__ hA,
                                                              float* __restrict__ hB,
                                                              float* __restrict__ UT)
{
    extern __shared__ float dyn[];
    float* wS  = dyn;                 // wS[k*16 + n], k=0..2047, n=0..15
    float* red = dyn + RES_ * 16;     // red[(n*16 + w)*32 + b]

    const int tid  = threadIdx.x;
    const int w    = tid >> 5;
    const int lane = tid & 31;
    const int n0   = blockIdx.x * 16;
    const int k0   = w * 128;

    // ---- one-time: cache W_hat[n0..n0+15][0..2047] into SMEM (transposed) ----
    {
        int n = tid >> 5;  // 0..15
        const float* row = Wh + (size_t)(n0 + n) * RES_;
#pragma unroll
        for (int j = 0; j < 16; j++) {
            int k = j * 128 + lane * 4;
            float4 v = *(const float4*)(row + k);
            wS[(k + 0) * 16 + n] = v.x;
            wS[(k + 1) * 16 + n] = v.y;
            wS[(k + 2) * 16 + n] = v.z;
            wS[(k + 3) * 16 + n] = v.w;
        }
    }
    __syncthreads();

    for (int t = 0; t < T_; t++) {
        const float* hin  = (t & 1) ? hB : hA;
        float*       hout = (t & 1) ? hA : hB;
        float*       Ut   = UT + (size_t)t * (RES_ * B_);

        float acc[16];
#pragma unroll
        for (int n = 0; n < 16; n++) acc[n] = 0.f;

        const float* hp = hin + (size_t)k0 * B_ + lane;
#pragma unroll 4
        for (int kb = 0; kb < 128; kb += 8) {
            float hv[8];
#pragma unroll
            for (int u = 0; u < 8; u++) hv[u] = hp[(kb + u) * B_];
#pragma unroll
            for (int u = 0; u < 8; u++) {
                const float* wr = &wS[(k0 + kb + u) * 16];
                float4 w0 = *(const float4*)(wr + 0);
                float4 w1 = *(const float4*)(wr + 4);
                float4 w2 = *(const float4*)(wr + 8);
                float4 w3 = *(const float4*)(wr + 12);
                float h = hv[u];
                acc[0]  = fmaf(w0.x, h, acc[0]);
                acc[1]  = fmaf(w0.y, h, acc[1]);
                acc[2]  = fmaf(w0.z, h, acc[2]);
                acc[3]  = fmaf(w0.w, h, acc[3]);
                acc[4]  = fmaf(w1.x, h, acc[4]);
                acc[5]  = fmaf(w1.y, h, acc[5]);
                acc[6]  = fmaf(w1.z, h, acc[6]);
                acc[7]  = fmaf(w1.w, h, acc[7]);
                acc[8]  = fmaf(w2.x, h, acc[8]);
                acc[9]  = fmaf(w2.y, h, acc[9]);
                acc[10] = fmaf(w2.z, h, acc[10]);
                acc[11] = fmaf(w2.w, h, acc[11]);
                acc[12] = fmaf(w3.x, h, acc[12]);
                acc[13] = fmaf(w3.y, h, acc[13]);
                acc[14] = fmaf(w3.z, h, acc[14]);
                acc[15] = fmaf(w3.w, h, acc[15]);
            }
        }

        // cross-warp reduction
#pragma unroll
        for (int n = 0; n < 16; n++) red[(n * 16 + w) * 32 + lane] = acc[n];
        __syncthreads();

        {
            int n = tid >> 5;       // 0..15
            int b = tid & 31;
            float s = 0.f;
#pragma unroll
            for (int ww = 0; ww < 16; ww++) s += red[(n * 16 + ww) * 32 + b];
            int off = (n0 + n) * B_ + b;
            float u    = Ut[off];
            float hn   = 0.5f * hin[off] + 0.5f * tanhf(s + u);
            hout[off]  = hn;
            Ut[off]    = hn;   // hsT for readout
        }
        __syncthreads();      // red reuse next step
        grid_barrier();       // hout visible chip-wide before next step reads it
    }
}

// ---------------- fused SGEMM-NT + bias + (GELU) readout ----------------
__device__ __forceinline__ float gelu_f(float v)
{
    return 0.5f * v * (1.0f + erff(v * 0.70710678118654752f));
}

// C[m][n] = act( sum_k A[m][k] * W[n][k] + bias[n] )
// A_MODE 0: A is hsT layout, A[m][k] at (m>>5)*RES*32 + k*32 + (m&31)  (K must be 2048)
// A_MODE 1: A row-major, lda = K
// OUT_MODE 0: C row-major [m][ldc]
// OUT_MODE 1: final output scatter: C[b*T*64 + t*64 + n], m = t*32 + b (n0 must be 0)
template <int A_MODE, int ACT, int OUT_MODE>
__global__ void __launch_bounds__(256) gemm_kernel(const float* __restrict__ A, int K,
                                                   const float* __restrict__ W,
                                                   const float* __restrict__ bias,
                                                   float* __restrict__ C, int ldc)
{
    __shared__ float As[16][132];
    __shared__ float Ws[16][64];
    const int m0  = blockIdx.x * 128;
    const int n0  = blockIdx.y * 64;
    const int tid = threadIdx.x;
    const int tx  = tid & 15;   // n: 4 each
    const int ty  = tid >> 4;   // m: 8 each

    float c[8][4];
#pragma unroll
    for (int i = 0; i < 8; i++)
#pragma unroll
        for (int j = 0; j < 4; j++) c[i][j] = 0.f;

    for (int k0 = 0; k0 < K; k0 += 16) {
        if (A_MODE == 0) {
            int base = tid * 8;
            int b    = base & 31;           // multiple of 8
            int kk   = (base >> 5) & 15;
            int tt   = base >> 9;
            const float* src = A + ((size_t)(m0 >> 5) + tt) * (RES_ * B_) +
                               (size_t)(k0 + kk) * B_ + b;
            float4 v0 = *(const float4*)src;
            float4 v1 = *(const float4*)(src + 4);
            int mm = tt * 32 + b;
            *(float4*)&As[kk][mm]     = v0;
            *(float4*)&As[kk][mm + 4] = v1;
        } else {
            int mm = tid >> 1, kk = (tid & 1) * 8;
            const float* src = A + (size_t)(m0 + mm) * K + k0 + kk;
            float4 v0 = *(const float4*)src;
            float4 v1 = *(const float4*)(src + 4);
            As[kk + 0][mm] = v0.x; As[kk + 1][mm] = v0.y;
            As[kk + 2][mm] = v0.z; As[kk + 3][mm] = v0.w;
            As[kk + 4][mm] = v1.x; As[kk + 5][mm] = v1.y;
            As[kk + 6][mm] = v1.z; As[kk + 7][mm] = v1.w;
        }
        {
            int n = tid >> 2, kq = (tid & 3) * 4;
            const float* src = W + (size_t)(n0 + n) * K + k0 + kq;
            float4 v = *(const float4*)src;
            Ws[kq + 0][n] = v.x; Ws[kq + 1][n] = v.y;
            Ws[kq + 2][n] = v.z; Ws[kq + 3][n] = v.w;
        }
        __syncthreads();
#pragma unroll
        for (int kk = 0; kk < 16; kk++) {
            float4 a0  = *(const float4*)&As[kk][ty * 8];
            float4 a1v = *(const float4*)&As[kk][ty * 8 + 4];
            float4 wv  = *(const float4*)&Ws[kk][tx * 4];
            float av[8] = {a0.x, a0.y, a0.z, a0.w, a1v.x, a1v.y, a1v.z, a1v.w};
            float wr[4] = {wv.x, wv.y, wv.z, wv.w};
#pragma unroll
            for (int i = 0; i < 8; i++)
#pragma unroll
                for (int j = 0; j < 4; j++)
                    c[i][j] = fmaf(av[i], wr[j], c[i][j]);
        }
        __syncthreads();
    }

    float bv[4];
#pragma unroll
    for (int j = 0; j < 4; j++) bv[j] = bias[n0 + tx * 4 + j];

#pragma unroll
    for (int i = 0; i < 8; i++) {
        float r[4];
#pragma unroll
        for (int j = 0; j < 4; j++) {
            float v = c[i][j] + bv[j];
            r[j] = (ACT == 1) ? gelu_f(v) : v;
        }
        float4 v4 = make_float4(r[0], r[1], r[2], r[3]);
        int m = m0 + ty * 8 + i;
        if (OUT_MODE == 0) {
            *(float4*)(C + (size_t)m * ldc + n0 + tx * 4) = v4;
        } else {
            int t = m >> 5, b = m & 31;
            *(float4*)(C + (size_t)b * (T_ * OUT_) + (size_t)t * OUT_ + tx * 4) = v4;
        }
    }
}

// ---------------- h_n: transpose hsT[1023][r][b] -> out[b][r] ----------------
__global__ void hn_kernel(const float* __restrict__ hT, float* __restrict__ out)
{
    int i = blockIdx.x * 256 + threadIdx.x;   // 65536 total
    int r = i >> 5, b = i & 31;
    out[(size_t)b * RES_ + r] = hT[i];
}

// ---------------- launch ----------------
extern "C" void kernel_launch(void* const* d_in, const int* in_sizes, int n_in,
                              void* d_out, int out_size)
{
    const float* x    = (const float*)d_in[0];
    const float* Win  = (const float*)d_in[1];
    const float* Wh   = (const float*)d_in[2];
    const float* W0   = (const float*)d_in[3];
    const float* b0   = (const float*)d_in[4];
    const float* W1   = (const float*)d_in[5];
    const float* b1   = (const float*)d_in[6];
    const float* W2   = (const float*)d_in[7];
    const float* b2   = (const float*)d_in[8];
    float*       out  = (float*)d_out;

    float *UT, *h0, *h1, *a1, *a2;
    cudaGetSymbolAddress((void**)&UT, g_UT);
    cudaGetSymbolAddress((void**)&h0, g_h0);
    cudaGetSymbolAddress((void**)&h1, g_h1);
    cudaGetSymbolAddress((void**)&a1, g_a1);
    cudaGetSymbolAddress((void**)&a2, g_a2);

    const int SCAN_SMEM = (RES_ * 16 + 16 * 16 * 32) * (int)sizeof(float);  // 160 KB
    cudaFuncSetAttribute(scan_persistent_kernel,
                         cudaFuncAttributeMaxDynamicSharedMemorySize, SCAN_SMEM);

    // 1) input projection, transposed layout UT[t][r][b]
    u_kernel<<<dim3(16, 1024), 256>>>(x, Win, UT);

    // 2) h0 = 0
    cudaMemsetAsync(h0, 0, (size_t)RES_ * B_ * sizeof(float));

    // 3) full sequential ESN scan in ONE persistent launch (device-wide barriers)
    scan_persistent_kernel<<<NCTA_, 512, SCAN_SMEM>>>(Wh, h0, h1, UT);

    // 4) readout MLP
    gemm_kernel<0, 1, 0><<<dim3(BT_ / 128, HID_ / 64), 256>>>(UT, RES_, W0, b0, a1, HID_);
    gemm_kernel<1, 1, 0><<<dim3(BT_ / 128, HID_ / 64), 256>>>(a1, HID_, W1, b1, a2, HID_);
    gemm_kernel<1, 0, 1><<<dim3(BT_ / 128, 1), 256>>>(a2, HID_, W2, b2, out, OUT_);

    // 5) h_n = hs[T-1], transposed to (B, RES)
    if (out_size >= (int)((size_t)B_ * T_ * OUT_ + (size_t)B_ * RES_)) {
        hn_kernel<<<RES_ * B_ / 256, 256>>>(UT + (size_t)(T_ - 1) * (RES_ * B_),
                                            out + (size_t)B_ * T_ * OUT_);
    }
}

// round 3
// speedup vs baseline: 1.0305x; 1.0305x over previous
#include <cuda_runtime.h>
#include <math.h>

#define B_   32
#define T_   1024
#define IN_  64
#define RES_ 2048
#define HID_ 512
#define OUT_ 64
#define BT_  (B_ * T_)
#define NCTA_ 128

typedef unsigned long long ull;

// ---- packed fp32x2 helpers (Blackwell dual-rate fp32) ----
__device__ __forceinline__ void ffma2(ull& d, ull a, ull b)
{
    asm("fma.rn.f32x2 %0, %1, %2, %0;" : "+l"(d) : "l"(a), "l"(b));
}
__device__ __forceinline__ ull splat2(float h)
{
    ull r;
    asm("mov.b64 %0, {%1, %1};" : "=l"(r) : "f"(h));
    return r;
}
__device__ __forceinline__ void unpack2(ull v, float& lo, float& hi)
{
    asm("mov.b64 {%0, %1}, %2;" : "=f"(lo), "=f"(hi) : "l"(v));
}

// ---------------- scratch (device globals; no allocation allowed) ----------------
__device__ float g_UT[(size_t)T_ * RES_ * B_];   // UT[t][r][b]; overwritten in place with hsT
__device__ float g_h0[RES_ * B_];                // hT ping
__device__ float g_h1[RES_ * B_];                // hT pong
__device__ float g_a1[(size_t)BT_ * HID_];       // readout act 1, row-major [m][512]
__device__ float g_a2[(size_t)BT_ * HID_];       // readout act 2
__device__ unsigned g_bar_count = 0;
__device__ unsigned g_bar_gen   = 0;

// ---------------- U = x @ W_in^T, stored transposed: UT[t][r][b] ----------------
__global__ void __launch_bounds__(256) u_kernel(const float* __restrict__ x,
                                                const float* __restrict__ Win,
                                                float* __restrict__ UT)
{
    __shared__ float xS[IN_][B_];
    __shared__ float wS[IN_][128];
    const int t   = blockIdx.y;
    const int R0  = blockIdx.x * 128;
    const int tid = threadIdx.x;

    {
        int b  = tid >> 3;
        int iq = (tid & 7) * 8;
        const float* src = x + (size_t)b * (T_ * IN_) + (size_t)t * IN_ + iq;
        float4 v0 = *(const float4*)(src);
        float4 v1 = *(const float4*)(src + 4);
        xS[iq + 0][b] = v0.x; xS[iq + 1][b] = v0.y; xS[iq + 2][b] = v0.z; xS[iq + 3][b] = v0.w;
        xS[iq + 4][b] = v1.x; xS[iq + 5][b] = v1.y; xS[iq + 6][b] = v1.z; xS[iq + 7][b] = v1.w;
    }
    {
        int r  = tid >> 1;
        int ih = (tid & 1) * 32;
        const float* src = Win + (size_t)(R0 + r) * IN_ + ih;
#pragma unroll
        for (int j = 0; j < 32; j += 4) {
            float4 v = *(const float4*)(src + j);
            wS[ih + j + 0][r] = v.x; wS[ih + j + 1][r] = v.y;
            wS[ih + j + 2][r] = v.z; wS[ih + j + 3][r] = v.w;
        }
    }
    __syncthreads();

    const int tx = tid & 7, ty = tid >> 3;
    const int b0 = tx * 4, r0 = ty * 4;
    float acc[4][4];
#pragma unroll
    for (int i = 0; i < 4; i++)
#pragma unroll
        for (int j = 0; j < 4; j++) acc[i][j] = 0.f;

#pragma unroll
    for (int i = 0; i < IN_; i++) {
        float4 xv = *(const float4*)&xS[i][b0];
        float4 wv = *(const float4*)&wS[i][r0];
        float xa[4] = {xv.x, xv.y, xv.z, xv.w};
        float wa[4] = {wv.x, wv.y, wv.z, wv.w};
#pragma unroll
        for (int ri = 0; ri < 4; ri++)
#pragma unroll
            for (int bi = 0; bi < 4; bi++)
                acc[ri][bi] = fmaf(wa[ri], xa[bi], acc[ri][bi]);
    }
    float* dst = UT + (size_t)t * (RES_ * B_);
#pragma unroll
    for (int ri = 0; ri < 4; ri++) {
        float4 v = make_float4(acc[ri][0], acc[ri][1], acc[ri][2], acc[ri][3]);
        *(float4*)(dst + (size_t)(R0 + r0 + ri) * B_ + b0) = v;
    }
}

// ---------------- device-wide barrier (all NCTA_ CTAs resident: 1 CTA/SM) ----------------
__device__ __forceinline__ void grid_barrier()
{
    __threadfence();
    __syncthreads();
    if (threadIdx.x == 0) {
        volatile unsigned* vgen = &g_bar_gen;
        unsigned old = *vgen;
        unsigned ticket = atomicAdd(&g_bar_count, 1u);
        if (ticket == NCTA_ - 1) {
            g_bar_count = 0;
            __threadfence();
            atomicAdd(&g_bar_gen, 1u);
        } else {
            while (*vgen == old) { __nanosleep(32); }
        }
        __threadfence();
    }
    __syncthreads();
}

// ---------------- persistent ESN scan, f32x2 packed FFMA ----------------
// 128 CTAs x 512 threads, CTA owns 16 output rows; W slice (16x2048) lives in SMEM.
// acc2[j] packs output rows (2j, 2j+1); W pairs are adjacent in wS[k*16+n].
__global__ void __launch_bounds__(512) scan_persistent_kernel(const float* __restrict__ Wh,
                                                              float* __restrict__ hA,
                                                              float* __restrict__ hB,
                                                              float* __restrict__ UT)
{
    extern __shared__ float dyn[];
    float* wS  = dyn;                 // wS[k*16 + n]
    float* red = dyn + RES_ * 16;     // red[(n*16 + w)*32 + b]

    const int tid  = threadIdx.x;
    const int w    = tid >> 5;
    const int lane = tid & 31;
    const int n0   = blockIdx.x * 16;
    const int k0   = w * 128;

    // one-time: cache W_hat[n0..n0+15][:] transposed into SMEM
    {
        int n = tid >> 5;
        const float* row = Wh + (size_t)(n0 + n) * RES_;
#pragma unroll
        for (int j = 0; j < 16; j++) {
            int k = j * 128 + lane * 4;
            float4 v = *(const float4*)(row + k);
            wS[(k + 0) * 16 + n] = v.x;
            wS[(k + 1) * 16 + n] = v.y;
            wS[(k + 2) * 16 + n] = v.z;
            wS[(k + 3) * 16 + n] = v.w;
        }
    }
    __syncthreads();

    for (int t = 0; t < T_; t++) {
        const float* hin  = (t & 1) ? hB : hA;
        float*       hout = (t & 1) ? hA : hB;
        float*       Ut   = UT + (size_t)t * (RES_ * B_);

        ull acc2[8];
#pragma unroll
        for (int j = 0; j < 8; j++) acc2[j] = 0ull;

        const float* hp = hin + (size_t)k0 * B_ + lane;
#pragma unroll 4
        for (int kb = 0; kb < 128; kb += 8) {
            float hv[8];
#pragma unroll
            for (int u = 0; u < 8; u++) hv[u] = hp[(kb + u) * B_];
#pragma unroll
            for (int u = 0; u < 8; u++) {
                const ull* wr = (const ull*)&wS[(k0 + kb + u) * 16];
                ulonglong2 p0 = *(const ulonglong2*)(wr + 0);  // rows 0-3
                ulonglong2 p1 = *(const ulonglong2*)(wr + 2);  // rows 4-7
                ulonglong2 p2 = *(const ulonglong2*)(wr + 4);  // rows 8-11
                ulonglong2 p3 = *(const ulonglong2*)(wr + 6);  // rows 12-15
                ull hh = splat2(hv[u]);
                ffma2(acc2[0], p0.x, hh);
                ffma2(acc2[1], p0.y, hh);
                ffma2(acc2[2], p1.x, hh);
                ffma2(acc2[3], p1.y, hh);
                ffma2(acc2[4], p2.x, hh);
                ffma2(acc2[5], p2.y, hh);
                ffma2(acc2[6], p3.x, hh);
                ffma2(acc2[7], p3.y, hh);
            }
        }

        // cross-warp reduction
#pragma unroll
        for (int j = 0; j < 8; j++) {
            float lo, hi;
            unpack2(acc2[j], lo, hi);
            red[((2 * j + 0) * 16 + w) * 32 + lane] = lo;
            red[((2 * j + 1) * 16 + w) * 32 + lane] = hi;
        }
        __syncthreads();

        {
            int n = tid >> 5;
            int b = tid & 31;
            float s = 0.f;
#pragma unroll
            for (int ww = 0; ww < 16; ww++) s += red[(n * 16 + ww) * 32 + b];
            int off = (n0 + n) * B_ + b;
            float u    = Ut[off];
            float hn   = 0.5f * hin[off] + 0.5f * tanhf(s + u);
            hout[off]  = hn;
            Ut[off]    = hn;
        }
        __syncthreads();
        grid_barrier();
    }
}

// ---------------- fused SGEMM-NT + bias + (GELU), f32x2 packed ----------------
__device__ __forceinline__ float gelu_f(float v)
{
    return 0.5f * v * (1.0f + erff(v * 0.70710678118654752f));
}

// C[m][n] = act( sum_k A[m][k] * W[n][k] + bias[n] )
// A_MODE 0: A in hsT layout (K must be 2048). A_MODE 1: row-major, lda=K.
// OUT_MODE 0: row-major. OUT_MODE 1: scatter to (b,t,n) with m = t*32+b.
template <int A_MODE, int ACT, int OUT_MODE>
__global__ void __launch_bounds__(256) gemm_kernel(const float* __restrict__ A, int K,
                                                   const float* __restrict__ W,
                                                   const float* __restrict__ bias,
                                                   float* __restrict__ C, int ldc)
{
    __shared__ float As[16][132];   // row stride 528B (16B-aligned)
    __shared__ float Ws[16][64];
    const int m0  = blockIdx.x * 128;
    const int n0  = blockIdx.y * 64;
    const int tid = threadIdx.x;
    const int tx  = tid & 15;   // n: 4 each
    const int ty  = tid >> 4;   // m: 8 each

    // c2[ip][j] packs m-rows (2ip, 2ip+1) for output col j
    ull c2[4][4];
#pragma unroll
    for (int i = 0; i < 4; i++)
#pragma unroll
        for (int j = 0; j < 4; j++) c2[i][j] = 0ull;

    for (int k0 = 0; k0 < K; k0 += 16) {
        if (A_MODE == 0) {
            int base = tid * 8;
            int b    = base & 31;
            int kk   = (base >> 5) & 15;
            int tt   = base >> 9;
            const float* src = A + ((size_t)(m0 >> 5) + tt) * (RES_ * B_) +
                               (size_t)(k0 + kk) * B_ + b;
            float4 v0 = *(const float4*)src;
            float4 v1 = *(const float4*)(src + 4);
            int mm = tt * 32 + b;
            *(float4*)&As[kk][mm]     = v0;
            *(float4*)&As[kk][mm + 4] = v1;
        } else {
            int mm = tid >> 1, kk = (tid & 1) * 8;
            const float* src = A + (size_t)(m0 + mm) * K + k0 + kk;
            float4 v0 = *(const float4*)src;
            float4 v1 = *(const float4*)(src + 4);
            As[kk + 0][mm] = v0.x; As[kk + 1][mm] = v0.y;
            As[kk + 2][mm] = v0.z; As[kk + 3][mm] = v0.w;
            As[kk + 4][mm] = v1.x; As[kk + 5][mm] = v1.y;
            As[kk + 6][mm] = v1.z; As[kk + 7][mm] = v1.w;
        }
        {
            int n = tid >> 2, kq = (tid & 3) * 4;
            const float* src = W + (size_t)(n0 + n) * K + k0 + kq;
            float4 v = *(const float4*)src;
            Ws[kq + 0][n] = v.x; Ws[kq + 1][n] = v.y;
            Ws[kq + 2][n] = v.z; Ws[kq + 3][n] = v.w;
        }
        __syncthreads();
#pragma unroll
        for (int kk = 0; kk < 16; kk++) {
            ulonglong2 a01 = *(const ulonglong2*)&As[kk][ty * 8];     // m-pairs 0,1
            ulonglong2 a23 = *(const ulonglong2*)&As[kk][ty * 8 + 4]; // m-pairs 2,3
            float4 wv = *(const float4*)&Ws[kk][tx * 4];
            ull w0 = splat2(wv.x), w1 = splat2(wv.y), w2 = splat2(wv.z), w3 = splat2(wv.w);
            ffma2(c2[0][0], a01.x, w0); ffma2(c2[0][1], a01.x, w1);
            ffma2(c2[0][2], a01.x, w2); ffma2(c2[0][3], a01.x, w3);
            ffma2(c2[1][0], a01.y, w0); ffma2(c2[1][1], a01.y, w1);
            ffma2(c2[1][2], a01.y, w2); ffma2(c2[1][3], a01.y, w3);
            ffma2(c2[2][0], a23.x, w0); ffma2(c2[2][1], a23.x, w1);
            ffma2(c2[2][2], a23.x, w2); ffma2(c2[2][3], a23.x, w3);
            ffma2(c2[3][0], a23.y, w0); ffma2(c2[3][1], a23.y, w1);
            ffma2(c2[3][2], a23.y, w2); ffma2(c2[3][3], a23.y, w3);
        }
        __syncthreads();
    }

    float bv[4];
#pragma unroll
    for (int j = 0; j < 4; j++) bv[j] = bias[n0 + tx * 4 + j];

#pragma unroll
    for (int ip = 0; ip < 4; ip++) {
#pragma unroll
        for (int half = 0; half < 2; half++) {
            float r[4];
#pragma unroll
            for (int j = 0; j < 4; j++) {
                float lo, hi;
                unpack2(c2[ip][j], lo, hi);
                float v = (half == 0 ? lo : hi) + bv[j];
                r[j] = (ACT == 1) ? gelu_f(v) : v;
            }
            float4 v4 = make_float4(r[0], r[1], r[2], r[3]);
            int m = m0 + ty * 8 + ip * 2 + half;
            if (OUT_MODE == 0) {
                *(float4*)(C + (size_t)m * ldc + n0 + tx * 4) = v4;
            } else {
                int t = m >> 5, b = m & 31;
                *(float4*)(C + (size_t)b * (T_ * OUT_) + (size_t)t * OUT_ + tx * 4) = v4;
            }
        }
    }
}

// ---------------- h_n: transpose hsT[1023][r][b] -> out[b][r] ----------------
__global__ void hn_kernel(const float* __restrict__ hT, float* __restrict__ out)
{
    int i = blockIdx.x * 256 + threadIdx.x;
    int r = i >> 5, b = i & 31;
    out[(size_t)b * RES_ + r] = hT[i];
}

// ---------------- launch ----------------
extern "C" void kernel_launch(void* const* d_in, const int* in_sizes, int n_in,
                              void* d_out, int out_size)
{
    const float* x    = (const float*)d_in[0];
    const float* Win  = (const float*)d_in[1];
    const float* Wh   = (const float*)d_in[2];
    const float* W0   = (const float*)d_in[3];
    const float* b0   = (const float*)d_in[4];
    const float* W1   = (const float*)d_in[5];
    const float* b1   = (const float*)d_in[6];
    const float* W2   = (const float*)d_in[7];
    const float* b2   = (const float*)d_in[8];
    float*       out  = (float*)d_out;

    float *UT, *h0, *h1, *a1, *a2;
    cudaGetSymbolAddress((void**)&UT, g_UT);
    cudaGetSymbolAddress((void**)&h0, g_h0);
    cudaGetSymbolAddress((void**)&h1, g_h1);
    cudaGetSymbolAddress((void**)&a1, g_a1);
    cudaGetSymbolAddress((void**)&a2, g_a2);

    const int SCAN_SMEM = (RES_ * 16 + 16 * 16 * 32) * (int)sizeof(float);  // 160 KB
    cudaFuncSetAttribute(scan_persistent_kernel,
                         cudaFuncAttributeMaxDynamicSharedMemorySize, SCAN_SMEM);

    u_kernel<<<dim3(16, 1024), 256>>>(x, Win, UT);
    cudaMemsetAsync(h0, 0, (size_t)RES_ * B_ * sizeof(float));

    scan_persistent_kernel<<<NCTA_, 512, SCAN_SMEM>>>(Wh, h0, h1, UT);

    gemm_kernel<0, 1, 0><<<dim3(BT_ / 128, HID_ / 64), 256>>>(UT, RES_, W0, b0, a1, HID_);
    gemm_kernel<1, 1, 0><<<dim3(BT_ / 128, HID_ / 64), 256>>>(a1, HID_, W1, b1, a2, HID_);
    gemm_kernel<1, 0, 1><<<dim3(BT_ / 128, 1), 256>>>(a2, HID_, W2, b2, out, OUT_);

    if (out_size >= (int)((size_t)B_ * T_ * OUT_ + (size_t)B_ * RES_)) {
        hn_kernel<<<RES_ * B_ / 256, 256>>>(UT + (size_t)(T_ - 1) * (RES_ * B_),
                                            out + (size_t)B_ * T_ * OUT_);
    }
}

// round 5
// speedup vs baseline: 1.0324x; 1.0019x over previous
#include <cuda_runtime.h>
#include <math.h>

#define B_   32
#define T_   1024
#define IN_  64
#define RES_ 2048
#define HID_ 512
#define OUT_ 64
#define BT_  (B_ * T_)
#define NCTA_ 128

typedef unsigned long long ull;

// ---- packed fp32x2 helpers ----
__device__ __forceinline__ void ffma2(ull& d, ull a, ull b)
{
    asm("fma.rn.f32x2 %0, %1, %2, %0;" : "+l"(d) : "l"(a), "l"(b));
}
__device__ __forceinline__ ull splat2(float h)
{
    ull r;
    asm("mov.b64 %0, {%1, %1};" : "=l"(r) : "f"(h));
    return r;
}
__device__ __forceinline__ void unpack2(ull v, float& lo, float& hi)
{
    asm("mov.b64 {%0, %1}, %2;" : "=f"(lo), "=f"(hi) : "l"(v));
}

// ---------------- scratch ----------------
__device__ float g_UT[(size_t)T_ * RES_ * B_];
__device__ float g_h0[RES_ * B_];
__device__ float g_h1[RES_ * B_];
__device__ float g_a1[(size_t)BT_ * HID_];
__device__ float g_a2[(size_t)BT_ * HID_];
__device__ unsigned g_bar_count = 0;
__device__ unsigned g_bar_gen   = 0;

// ---------------- U = x @ W_in^T -> UT[t][r][b] ----------------
__global__ void __launch_bounds__(256) u_kernel(const float* __restrict__ x,
                                                const float* __restrict__ Win,
                                                float* __restrict__ UT)
{
    __shared__ float xS[IN_][B_];
    __shared__ float wS[IN_][128];
    const int t   = blockIdx.y;
    const int R0  = blockIdx.x * 128;
    const int tid = threadIdx.x;

    {
        int b  = tid >> 3;
        int iq = (tid & 7) * 8;
        const float* src = x + (size_t)b * (T_ * IN_) + (size_t)t * IN_ + iq;
        float4 v0 = *(const float4*)(src);
        float4 v1 = *(const float4*)(src + 4);
        xS[iq + 0][b] = v0.x; xS[iq + 1][b] = v0.y; xS[iq + 2][b] = v0.z; xS[iq + 3][b] = v0.w;
        xS[iq + 4][b] = v1.x; xS[iq + 5][b] = v1.y; xS[iq + 6][b] = v1.z; xS[iq + 7][b] = v1.w;
    }
    {
        int r  = tid >> 1;
        int ih = (tid & 1) * 32;
        const float* src = Win + (size_t)(R0 + r) * IN_ + ih;
#pragma unroll
        for (int j = 0; j < 32; j += 4) {
            float4 v = *(const float4*)(src + j);
            wS[ih + j + 0][r] = v.x; wS[ih + j + 1][r] = v.y;
            wS[ih + j + 2][r] = v.z; wS[ih + j + 3][r] = v.w;
        }
    }
    __syncthreads();

    const int tx = tid & 7, ty = tid >> 3;
    const int b0 = tx * 4, r0 = ty * 4;
    float acc[4][4];
#pragma unroll
    for (int i = 0; i < 4; i++)
#pragma unroll
        for (int j = 0; j < 4; j++) acc[i][j] = 0.f;

#pragma unroll
    for (int i = 0; i < IN_; i++) {
        float4 xv = *(const float4*)&xS[i][b0];
        float4 wv = *(const float4*)&wS[i][r0];
        float xa[4] = {xv.x, xv.y, xv.z, xv.w};
        float wa[4] = {wv.x, wv.y, wv.z, wv.w};
#pragma unroll
        for (int ri = 0; ri < 4; ri++)
#pragma unroll
            for (int bi = 0; bi < 4; bi++)
                acc[ri][bi] = fmaf(wa[ri], xa[bi], acc[ri][bi]);
    }
    float* dst = UT + (size_t)t * (RES_ * B_);
#pragma unroll
    for (int ri = 0; ri < 4; ri++) {
        float4 v = make_float4(acc[ri][0], acc[ri][1], acc[ri][2], acc[ri][3]);
        *(float4*)(dst + (size_t)(R0 + r0 + ri) * B_ + b0) = v;
    }
}

// ---------------- device-wide barrier ----------------
__device__ __forceinline__ void grid_barrier()
{
    __threadfence();
    __syncthreads();
    if (threadIdx.x == 0) {
        volatile unsigned* vgen = &g_bar_gen;
        unsigned old = *vgen;
        unsigned ticket = atomicAdd(&g_bar_count, 1u);
        if (ticket == NCTA_ - 1) {
            g_bar_count = 0;
            __threadfence();
            atomicAdd(&g_bar_gen, 1u);
        } else {
            while (*vgen == old) { __nanosleep(32); }
        }
        __threadfence();
    }
    __syncthreads();
}

// ---- 8-k FMA block: consumes hv[8], W from SMEM ----
__device__ __forceinline__ void fma_block8(ull acc2[8], const float* __restrict__ wS,
                                           int kbase, const float hv[8])
{
#pragma unroll
    for (int u = 0; u < 8; u++) {
        const ull* wr = (const ull*)&wS[(kbase + u) * 16];
        ulonglong2 p0 = *(const ulonglong2*)(wr + 0);
        ulonglong2 p1 = *(const ulonglong2*)(wr + 2);
        ulonglong2 p2 = *(const ulonglong2*)(wr + 4);
        ulonglong2 p3 = *(const ulonglong2*)(wr + 6);
        ull hh = splat2(hv[u]);
        ffma2(acc2[0], p0.x, hh);
        ffma2(acc2[1], p0.y, hh);
        ffma2(acc2[2], p1.x, hh);
        ffma2(acc2[3], p1.y, hh);
        ffma2(acc2[4], p2.x, hh);
        ffma2(acc2[5], p2.y, hh);
        ffma2(acc2[6], p3.x, hh);
        ffma2(acc2[7], p3.y, hh);
    }
}

// ---------------- persistent ESN scan, ping-pong h prefetch ----------------
__global__ void __launch_bounds__(512) scan_persistent_kernel(const float* __restrict__ Wh,
                                                              float* __restrict__ hA,
                                                              float* __restrict__ hB,
                                                              float* __restrict__ UT)
{
    extern __shared__ float dyn[];
    float* wS  = dyn;                 // wS[k*16 + n]
    float* red = dyn + RES_ * 16;     // red[(n*16 + w)*32 + b]

    const int tid  = threadIdx.x;
    const int w    = tid >> 5;
    const int lane = tid & 31;
    const int n0   = blockIdx.x * 16;
    const int k0   = w * 128;

    // one-time: cache W_hat slice transposed into SMEM
    {
        int n = tid >> 5;
        const float* row = Wh + (size_t)(n0 + n) * RES_;
#pragma unroll
        for (int j = 0; j < 16; j++) {
            int k = j * 128 + lane * 4;
            float4 v = *(const float4*)(row + k);
            wS[(k + 0) * 16 + n] = v.x;
            wS[(k + 1) * 16 + n] = v.y;
            wS[(k + 2) * 16 + n] = v.z;
            wS[(k + 3) * 16 + n] = v.w;
        }
    }
    // tail indices
    const int tn  = tid >> 5;
    const int tb  = tid & 31;
    const int toff = (n0 + tn) * B_ + tb;
    __syncthreads();

    for (int t = 0; t < T_; t++) {
        const float* hin  = (t & 1) ? hB : hA;
        float*       hout = (t & 1) ? hA : hB;
        float*       Ut   = UT + (size_t)t * (RES_ * B_);

        ull acc2[8];
#pragma unroll
        for (int j = 0; j < 8; j++) acc2[j] = 0ull;

        const float* hp = hin + (size_t)k0 * B_ + lane;

        // ---- ping-pong prefetch pipeline over 16 batches of 8 k ----
        float va[8], vb[8];
#pragma unroll
        for (int u = 0; u < 8; u++) va[u] = hp[u * B_];      // batch 0

#pragma unroll
        for (int kb = 0; kb < 128; kb += 16) {
            if (kb + 8 < 128) {
#pragma unroll
                for (int u = 0; u < 8; u++) vb[u] = hp[(kb + 8 + u) * B_];
            }
            fma_block8(acc2, wS, k0 + kb, va);
            if (kb + 16 < 128) {
#pragma unroll
                for (int u = 0; u < 8; u++) va[u] = hp[(kb + 16 + u) * B_];
            }
            fma_block8(acc2, wS, k0 + kb + 8, vb);
        }

        // prefetch tail operands (overlaps sync + reduction)
        float u_pref = Ut[toff];
        float hprev  = hin[toff];

        // cross-warp reduction
#pragma unroll
        for (int j = 0; j < 8; j++) {
            float lo, hi;
            unpack2(acc2[j], lo, hi);
            red[((2 * j + 0) * 16 + w) * 32 + lane] = lo;
            red[((2 * j + 1) * 16 + w) * 32 + lane] = hi;
        }
        __syncthreads();

        {
            float s = 0.f;
#pragma unroll
            for (int ww = 0; ww < 16; ww++) s += red[(tn * 16 + ww) * 32 + tb];
            float hn = 0.5f * hprev + 0.5f * tanhf(s + u_pref);
            hout[toff] = hn;
            Ut[toff]   = hn;
        }
        // grid_barrier's leading __syncthreads orders red reuse; no extra sync needed
        grid_barrier();
    }
}

// ---------------- fused SGEMM-NT + bias + (GELU), f32x2 packed ----------------
__device__ __forceinline__ float gelu_f(float v)
{
    return 0.5f * v * (1.0f + erff(v * 0.70710678118654752f));
}

template <int A_MODE, int ACT, int OUT_MODE>
__global__ void __launch_bounds__(256) gemm_kernel(const float* __restrict__ A, int K,
                                                   const float* __restrict__ W,
                                                   const float* __restrict__ bias,
                                                   float* __restrict__ C, int ldc)
{
    __shared__ float As[16][132];
    __shared__ float Ws[16][64];
    const int m0  = blockIdx.x * 128;
    const int n0  = blockIdx.y * 64;
    const int tid = threadIdx.x;
    const int tx  = tid & 15;
    const int ty  = tid >> 4;

    ull c2[4][4];
#pragma unroll
    for (int i = 0; i < 4; i++)
#pragma unroll
        for (int j = 0; j < 4; j++) c2[i][j] = 0ull;

    for (int k0 = 0; k0 < K; k0 += 16) {
        if (A_MODE == 0) {
            int base = tid * 8;
            int b    = base & 31;
            int kk   = (base >> 5) & 15;
            int tt   = base >> 9;
            const float* src = A + ((size_t)(m0 >> 5) + tt) * (RES_ * B_) +
                               (size_t)(k0 + kk) * B_ + b;
            float4 v0 = *(const float4*)src;
            float4 v1 = *(const float4*)(src + 4);
            int mm = tt * 32 + b;
            *(float4*)&As[kk][mm]     = v0;
            *(float4*)&As[kk][mm + 4] = v1;
        } else {
            int mm = tid >> 1, kk = (tid & 1) * 8;
            const float* src = A + (size_t)(m0 + mm) * K + k0 + kk;
            float4 v0 = *(const float4*)src;
            float4 v1 = *(const float4*)(src + 4);
            As[kk + 0][mm] = v0.x; As[kk + 1][mm] = v0.y;
            As[kk + 2][mm] = v0.z; As[kk + 3][mm] = v0.w;
            As[kk + 4][mm] = v1.x; As[kk + 5][mm] = v1.y;
            As[kk + 6][mm] = v1.z; As[kk + 7][mm] = v1.w;
        }
        {
            int n = tid >> 2, kq = (tid & 3) * 4;
            const float* src = W + (size_t)(n0 + n) * K + k0 + kq;
            float4 v = *(const float4*)src;
            Ws[kq + 0][n] = v.x; Ws[kq + 1][n] = v.y;
            Ws[kq + 2][n] = v.z; Ws[kq + 3][n] = v.w;
        }
        __syncthreads();
#pragma unroll
        for (int kk = 0; kk < 16; kk++) {
            ulonglong2 a01 = *(const ulonglong2*)&As[kk][ty * 8];
            ulonglong2 a23 = *(const ulonglong2*)&As[kk][ty * 8 + 4];
            float4 wv = *(const float4*)&Ws[kk][tx * 4];
            ull w0 = splat2(wv.x), w1 = splat2(wv.y), w2 = splat2(wv.z), w3 = splat2(wv.w);
            ffma2(c2[0][0], a01.x, w0); ffma2(c2[0][1], a01.x, w1);
            ffma2(c2[0][2], a01.x, w2); ffma2(c2[0][3], a01.x, w3);
            ffma2(c2[1][0], a01.y, w0); ffma2(c2[1][1], a01.y, w1);
            ffma2(c2[1][2], a01.y, w2); ffma2(c2[1][3], a01.y, w3);
            ffma2(c2[2][0], a23.x, w0); ffma2(c2[2][1], a23.x, w1);
            ffma2(c2[2][2], a23.x, w2); ffma2(c2[2][3], a23.x, w3);
            ffma2(c2[3][0], a23.y, w0); ffma2(c2[3][1], a23.y, w1);
            ffma2(c2[3][2], a23.y, w2); ffma2(c2[3][3], a23.y, w3);
        }
        __syncthreads();
    }

    float bv[4];
#pragma unroll
    for (int j = 0; j < 4; j++) bv[j] = bias[n0 + tx * 4 + j];

#pragma unroll
    for (int ip = 0; ip < 4; ip++) {
#pragma unroll
        for (int half = 0; half < 2; half++) {
            float r[4];
#pragma unroll
            for (int j = 0; j < 4; j++) {
                float lo, hi;
                unpack2(c2[ip][j], lo, hi);
                float v = (half == 0 ? lo : hi) + bv[j];
                r[j] = (ACT == 1) ? gelu_f(v) : v;
            }
            float4 v4 = make_float4(r[0], r[1], r[2], r[3]);
            int m = m0 + ty * 8 + ip * 2 + half;
            if (OUT_MODE == 0) {
                *(float4*)(C + (size_t)m * ldc + n0 + tx * 4) = v4;
            } else {
                int t = m >> 5, b = m & 31;
                *(float4*)(C + (size_t)b * (T_ * OUT_) + (size_t)t * OUT_ + tx * 4) = v4;
            }
        }
    }
}

// ---------------- h_n: transpose hsT[1023][r][b] -> out[b][r] ----------------
__global__ void hn_kernel(const float* __restrict__ hT, float* __restrict__ out)
{
    int i = blockIdx.x * 256 + threadIdx.x;
    int r = i >> 5, b = i & 31;
    out[(size_t)b * RES_ + r] = hT[i];
}

// ---------------- launch ----------------
extern "C" void kernel_launch(void* const* d_in, const int* in_sizes, int n_in,
                              void* d_out, int out_size)
{
    const float* x    = (const float*)d_in[0];
    const float* Win  = (const float*)d_in[1];
    const float* Wh   = (const float*)d_in[2];
    const float* W0   = (const float*)d_in[3];
    const float* b0   = (const float*)d_in[4];
    const float* W1   = (const float*)d_in[5];
    const float* b1   = (const float*)d_in[6];
    const float* W2   = (const float*)d_in[7];
    const float* b2   = (const float*)d_in[8];
    float*       out  = (float*)d_out;

    float *UT, *h0, *h1, *a1, *a2;
    cudaGetSymbolAddress((void**)&UT, g_UT);
    cudaGetSymbolAddress((void**)&h0, g_h0);
    cudaGetSymbolAddress((void**)&h1, g_h1);
    cudaGetSymbolAddress((void**)&a1, g_a1);
    cudaGetSymbolAddress((void**)&a2, g_a2);

    const int SCAN_SMEM = (RES_ * 16 + 16 * 16 * 32) * (int)sizeof(float);  // 160 KB
    cudaFuncSetAttribute(scan_persistent_kernel,
                         cudaFuncAttributeMaxDynamicSharedMemorySize, SCAN_SMEM);

    u_kernel<<<dim3(16, 1024), 256>>>(x, Win, UT);
    cudaMemsetAsync(h0, 0, (size_t)RES_ * B_ * sizeof(float));

    scan_persistent_kernel<<<NCTA_, 512, SCAN_SMEM>>>(Wh, h0, h1, UT);

    gemm_kernel<0, 1, 0><<<dim3(BT_ / 128, HID_ / 64), 256>>>(UT, RES_, W0, b0, a1, HID_);
    gemm_kernel<1, 1, 0><<<dim3(BT_ / 128, HID_ / 64), 256>>>(a1, HID_, W1, b1, a2, HID_);
    gemm_kernel<1, 0, 1><<<dim3(BT_ / 128, 1), 256>>>(a2, HID_, W2, b2, out, OUT_);

    if (out_size >= (int)((size_t)B_ * T_ * OUT_ + (size_t)B_ * RES_)) {
        hn_kernel<<<RES_ * B_ / 256, 256>>>(UT + (size_t)(T_ - 1) * (RES_ * B_),
                                            out + (size_t)B_ * T_ * OUT_);
    }
}